// round 10
// baseline (speedup 1.0000x reference)
#include <cuda_runtime.h>

// SSIM, fully fused, separable 11-tap Gaussian, streaming vertical ring accumulators.
// R7: f32x2 packed math (img1/img2 interleaved), division-free staging,
//     per-block partials (no zero kernel, no global atomics).
// Layout: 48 planes (16 batch x 3 ch) of 512x512 fp32.
// Grid: plane x 4 column-strips (128 cols) x 4 row-bands (128 rows) = 768 blocks.

#define IMG_H 512
#define IMG_W 512
#define NPLANES 48
#define TW 128
#define BAND 128
#define SROW2 139           // padded float2 smem row (need 138)
#define NCHUNKS 13          // 13*11 = 143 >= 138 input rows per band
#define NBLOCKS (NPLANES * 16)
#define C1F 0.0001f         // 0.01^2
#define C2F 0.0009f         // 0.03^2
#define INV_TOTAL (1.0 / 12582912.0)

typedef unsigned long long u64;

__device__ double g_partials[NBLOCKS];

__device__ __forceinline__ u64 pack2(float lo, float hi) {
    u64 r; asm("mov.b64 %0, {%1, %2};" : "=l"(r) : "f"(lo), "f"(hi)); return r;
}
__device__ __forceinline__ void unpack2(u64 v, float& lo, float& hi) {
    asm("mov.b64 {%0, %1}, %2;" : "=f"(lo), "=f"(hi) : "l"(v));
}
__device__ __forceinline__ u64 fma2(u64 a, u64 b, u64 c) {
    u64 d; asm("fma.rn.f32x2 %0, %1, %2, %3;" : "=l"(d) : "l"(a), "l"(b), "l"(c)); return d;
}
__device__ __forceinline__ u64 mul2(u64 a, u64 b) {
    u64 d; asm("mul.rn.f32x2 %0, %1, %2;" : "=l"(d) : "l"(a), "l"(b)); return d;
}

__global__ void ssim_finalize_kernel(float* out) {
    __shared__ double wsum[8];
    const int tid = threadIdx.x;
    double s = 0.0;
    for (int i = tid; i < NBLOCKS; i += 256) s += g_partials[i];
#pragma unroll
    for (int off = 16; off; off >>= 1)
        s += __shfl_xor_sync(0xffffffffu, s, off);
    if ((tid & 31) == 0) wsum[tid >> 5] = s;
    __syncthreads();
    if (tid == 0) {
        double t = 0.0;
#pragma unroll
        for (int w = 0; w < 8; w++) t += wsum[w];
        out[0] = (float)(t * INV_TOTAL);
    }
}

__global__ void __launch_bounds__(128, 4) ssim_main_kernel(
    const float* __restrict__ img1,
    const float* __restrict__ img2)
{
    const int tid   = threadIdx.x;
    const int bx    = blockIdx.x;
    const int strip = bx & 3;
    const int band  = (bx >> 2) & 3;
    const int plane = bx >> 4;

    const int c0 = strip * TW;
    const int R0 = band * BAND;
    const long planeOff = (long)plane * (IMG_H * IMG_W);
    const float* __restrict__ p1 = img1 + planeOff;
    const float* __restrict__ p2 = img2 + planeOff;

    // Interleaved (img1, img2) tiles: LDS.64 per tap instead of 2x LDS.32.
    __shared__ float2 s12[11][SROW2];

    // 1D Gaussian weights (sigma=1.5, K=11), normalized, compile-time constants.
    const float WW[11] = {
        0.00102838f, 0.00759876f, 0.03600077f, 0.10936069f, 0.21300554f,
        0.26601172f,
        0.21300554f, 0.10936069f, 0.03600077f, 0.00759876f, 0.00102838f
    };
    // Packed (W,W) weights; symmetry keeps it to 6 registers-pairs.
    u64 W2[6];
#pragma unroll
    for (int k = 0; k < 6; k++) W2[k] = pack2(WW[k], WW[k]);

    // Ring accumulators: slot j holds output row o with (o - ir0) mod 11 == j.
    // aAB packs (sum1, sum2); aSQ packs (sum11, sum22); a12 scalar.
    u64 aAB[11], aSQ[11];
    float a12[11];
#pragma unroll
    for (int j = 0; j < 11; j++) { aAB[j] = 0ull; aSQ[j] = 0ull; a12[j] = 0.f; }

    float ssum = 0.f;
    const int ir0 = R0 - 5;   // first input row needed

#pragma unroll 1
    for (int chunk = 0; chunk < NCHUNKS; chunk++) {
        __syncthreads();   // previous chunk's compute done before overwriting smem
        const int baseRow = ir0 + chunk * 11;
        // Division-free staging: per row, thread t loads col t; t<10 loads halo.
#pragma unroll
        for (int u = 0; u < 11; u++) {
            const int r = baseRow + u;
            const bool rok = (r >= 0) && (r < IMG_H);
            const int rowBase = r * IMG_W;
            {
                const int c = c0 - 5 + tid;
                float v1 = 0.f, v2 = 0.f;
                if (rok && c >= 0 && c < IMG_W) {
                    v1 = p1[rowBase + c];
                    v2 = p2[rowBase + c];
                }
                s12[u][tid] = make_float2(v1, v2);
            }
            if (tid < 10) {
                const int cc = TW + tid;
                const int c = c0 - 5 + cc;
                float v1 = 0.f, v2 = 0.f;
                if (rok && c < IMG_W) {        // c >= 0 always here
                    v1 = p1[rowBase + c];
                    v2 = p2[rowBase + c];
                }
                s12[u][cc] = make_float2(v1, v2);
            }
        }
        __syncthreads();

#pragma unroll
        for (int u = 0; u < 11; u++) {
            // ---- horizontal separable conv, f32x2 packed over (img1,img2) ----
            u64 hAB = 0ull, hSQ = 0ull;
            float h12 = 0.f;
#pragma unroll
            for (int k = 0; k < 11; k++) {
                const u64 v = *reinterpret_cast<const u64*>(&s12[u][tid + k]);
                const u64 w = W2[k < 6 ? k : 10 - k];
                hAB = fma2(v, w, hAB);               // (h1,h2)   += W*(a,b)
                const u64 sq = mul2(v, v);           // (a^2,b^2)
                hSQ = fma2(sq, w, hSQ);              // (h11,h22) += W*(a^2,b^2)
                float a, b; unpack2(v, a, b);
                h12 = fmaf(WW[k], a * b, h12);       // FFMA-imm
            }
            // ---- vertical scatter into ring accumulators (static indices) ----
#pragma unroll
            for (int j = 0; j < 11; j++) {
                const int k = (u + 5 - j + 11) % 11;   // compile-time per (u,j)
                const u64 w = W2[k < 6 ? k : 10 - k];
                aAB[j] = fma2(w, hAB, aAB[j]);
                aSQ[j] = fma2(w, hSQ, aSQ[j]);
                a12[j] = fmaf(WW[k], h12, a12[j]);     // FFMA-imm
            }
            // ---- output row o = R0 + t - 10 completes this iteration ----
            const int jc = (u + 6) % 11;               // compile-time per u
            const int t  = chunk * 11 + u;
            if (t >= 10 && t < 138) {
                float mu1, mu2, m11, m22;
                unpack2(aAB[jc], mu1, mu2);
                unpack2(aSQ[jc], m11, m22);
                const float mu1sq = mu1 * mu1;
                const float mu2sq = mu2 * mu2;
                const float mu12  = mu1 * mu2;
                const float sg1   = m11 - mu1sq;
                const float sg2   = m22 - mu2sq;
                const float sg12  = a12[jc] - mu12;
                const float num = (2.f * mu12 + C1F) * (2.f * sg12 + C2F);
                const float den = (mu1sq + mu2sq + C1F) * (sg1 + sg2 + C2F);
                ssum += __fdividef(num, den);
            }
            aAB[jc] = 0ull; aSQ[jc] = 0ull; a12[jc] = 0.f;
        }
    }

    // ---- reduction: warp shfl -> block -> per-block partial (no atomics) ----
#pragma unroll
    for (int off = 16; off; off >>= 1)
        ssum += __shfl_xor_sync(0xffffffffu, ssum, off);

    __shared__ float wsum[4];
    if ((tid & 31) == 0) wsum[tid >> 5] = ssum;
    __syncthreads();
    if (tid == 0) {
        g_partials[bx] = (double)wsum[0] + (double)wsum[1]
                       + (double)wsum[2] + (double)wsum[3];
    }
}

extern "C" void kernel_launch(void* const* d_in, const int* in_sizes, int n_in,
                              void* d_out, int out_size) {
    const float* img1 = (const float*)d_in[0];
    const float* img2 = (const float*)d_in[1];
    // d_in[2] (window) unused: weights baked in as compile-time constants.
    float* out = (float*)d_out;

    ssim_main_kernel<<<NBLOCKS, 128>>>(img1, img2);
    ssim_finalize_kernel<<<1, 256>>>(out);
}

// round 11
// speedup vs baseline: 1.2445x; 1.2445x over previous
#include <cuda_runtime.h>

// SSIM, fully fused, separable 11-tap Gaussian, streaming vertical ring accumulators.
// R10: scalar math only (f32x2 reverted), FFMA-imm horizontal pass, wave-exact
//      576-block grid (48 planes x 4 col-strips x 3 row-bands), interleaved
//      float2 smem (LDS.64), division-free staging, per-block partials.

#define IMG_H 512
#define IMG_W 512
#define NPLANES 48
#define TW 128
#define BANDROWS0 171        // bands 0,1 = 171 rows; band 2 = 170 rows
#define SROW2 139            // padded float2 smem row (need 138)
#define NCHUNKS 17           // 17*11 = 187 >= 181 staged rows per band
#define NBLOCKS (NPLANES * 4 * 3)
#define C1F 0.0001f          // 0.01^2
#define C2F 0.0009f          // 0.03^2
#define INV_TOTAL (1.0 / 12582912.0)

__device__ double g_partials[NBLOCKS];

__global__ void ssim_finalize_kernel(float* out) {
    __shared__ double wsum[8];
    const int tid = threadIdx.x;
    double s = 0.0;
    for (int i = tid; i < NBLOCKS; i += 256) s += g_partials[i];
#pragma unroll
    for (int off = 16; off; off >>= 1)
        s += __shfl_xor_sync(0xffffffffu, s, off);
    if ((tid & 31) == 0) wsum[tid >> 5] = s;
    __syncthreads();
    if (tid == 0) {
        double t = 0.0;
#pragma unroll
        for (int w = 0; w < 8; w++) t += wsum[w];
        out[0] = (float)(t * INV_TOTAL);
    }
}

__global__ void __launch_bounds__(128, 4) ssim_main_kernel(
    const float* __restrict__ img1,
    const float* __restrict__ img2)
{
    const int tid = threadIdx.x;
    const int bx  = blockIdx.x;
    // bx = plane*12 + strip*3 + band
    const int band  = bx % 3;
    const int strip = (bx / 3) & 3;
    const int plane = bx / 12;

    const int c0   = strip * TW;
    const int R0   = band * BANDROWS0;
    const int rows = (band == 2) ? (IMG_H - 2 * BANDROWS0) : BANDROWS0;

    const long planeOff = (long)plane * (IMG_H * IMG_W);
    const float* __restrict__ p1 = img1 + planeOff;
    const float* __restrict__ p2 = img2 + planeOff;

    // Interleaved (img1, img2): one LDS.64 per tap instead of 2x LDS.32.
    __shared__ float2 s12[11][SROW2];

    // 1D Gaussian weights (sigma=1.5, K=11), compile-time constants so every
    // FFMA with a WW[] multiplier takes the immediate form (rt=1 on sm_103a).
    const float WW[11] = {
        0.00102838f, 0.00759876f, 0.03600077f, 0.10936069f, 0.21300554f,
        0.26601172f,
        0.21300554f, 0.10936069f, 0.03600077f, 0.00759876f, 0.00102838f
    };

    // Ring accumulators: slot j holds output row o with (o - ir0) mod 11 == j.
    float a1[11], a2[11], a11[11], a22[11], a12[11];
#pragma unroll
    for (int j = 0; j < 11; j++) {
        a1[j] = 0.f; a2[j] = 0.f; a11[j] = 0.f; a22[j] = 0.f; a12[j] = 0.f;
    }

    float ssum = 0.f;
    const int ir0 = R0 - 5;          // first input row needed
    const int tmax = rows + 10;      // staged-row index of last output + 1

#pragma unroll 1
    for (int chunk = 0; chunk < NCHUNKS; chunk++) {
        __syncthreads();   // previous chunk's compute done before overwriting smem
        const int baseRow = ir0 + chunk * 11;
        // Division-free staging: per row, thread t loads col t; t<10 loads halo.
#pragma unroll
        for (int u = 0; u < 11; u++) {
            const int r = baseRow + u;
            const bool rok = (r >= 0) && (r < IMG_H);
            const int rowBase = r * IMG_W;
            {
                const int c = c0 - 5 + tid;
                float v1 = 0.f, v2 = 0.f;
                if (rok && c >= 0 && c < IMG_W) {
                    v1 = p1[rowBase + c];
                    v2 = p2[rowBase + c];
                }
                s12[u][tid] = make_float2(v1, v2);
            }
            if (tid < 10) {
                const int cc = TW + tid;
                const int c = c0 - 5 + cc;
                float v1 = 0.f, v2 = 0.f;
                if (rok && c < IMG_W) {      // c >= 0 always here
                    v1 = p1[rowBase + c];
                    v2 = p2[rowBase + c];
                }
                s12[u][cc] = make_float2(v1, v2);
            }
        }
        __syncthreads();

#pragma unroll
        for (int u = 0; u < 11; u++) {
            // ---- horizontal pass: 3 FMUL + 5 FFMA-imm per tap ----
            float h1 = 0.f, h2 = 0.f, h11 = 0.f, h22 = 0.f, h12 = 0.f;
#pragma unroll
            for (int k = 0; k < 11; k++) {
                const float2 v = s12[u][tid + k];
                const float a = v.x, b = v.y;
                const float aa = a * a;
                const float bb = b * b;
                const float ab = a * b;
                h1  = fmaf(a,  WW[k], h1);     // FFMA-imm
                h2  = fmaf(b,  WW[k], h2);     // FFMA-imm
                h11 = fmaf(aa, WW[k], h11);    // FFMA-imm
                h22 = fmaf(bb, WW[k], h22);    // FFMA-imm
                h12 = fmaf(ab, WW[k], h12);    // FFMA-imm
            }
            // ---- vertical scatter into ring accumulators (static indices) ----
#pragma unroll
            for (int j = 0; j < 11; j++) {
                const int k = (u + 5 - j + 11) % 11;   // compile-time per (u,j)
                a1[j]  = fmaf(h1,  WW[k], a1[j]);      // FFMA-imm
                a2[j]  = fmaf(h2,  WW[k], a2[j]);
                a11[j] = fmaf(h11, WW[k], a11[j]);
                a22[j] = fmaf(h22, WW[k], a22[j]);
                a12[j] = fmaf(h12, WW[k], a12[j]);
            }
            // ---- output row o = R0 + t - 10 completes this iteration ----
            const int jc = (u + 6) % 11;               // compile-time per u
            const int t  = chunk * 11 + u;
            if (t >= 10 && t < tmax) {
                const float mu1   = a1[jc];
                const float mu2   = a2[jc];
                const float mu1sq = mu1 * mu1;
                const float mu2sq = mu2 * mu2;
                const float mu12  = mu1 * mu2;
                const float sg1   = a11[jc] - mu1sq;
                const float sg2   = a22[jc] - mu2sq;
                const float sg12  = a12[jc] - mu12;
                const float num = (2.f * mu12 + C1F) * (2.f * sg12 + C2F);
                const float den = (mu1sq + mu2sq + C1F) * (sg1 + sg2 + C2F);
                ssum += __fdividef(num, den);
            }
            a1[jc] = 0.f; a2[jc] = 0.f; a11[jc] = 0.f; a22[jc] = 0.f; a12[jc] = 0.f;
        }
    }

    // ---- reduction: warp shfl -> block -> per-block partial (no atomics) ----
#pragma unroll
    for (int off = 16; off; off >>= 1)
        ssum += __shfl_xor_sync(0xffffffffu, ssum, off);

    __shared__ float wsum[4];
    if ((tid & 31) == 0) wsum[tid >> 5] = ssum;
    __syncthreads();
    if (tid == 0) {
        g_partials[bx] = (double)wsum[0] + (double)wsum[1]
                       + (double)wsum[2] + (double)wsum[3];
    }
}

extern "C" void kernel_launch(void* const* d_in, const int* in_sizes, int n_in,
                              void* d_out, int out_size) {
    const float* img1 = (const float*)d_in[0];
    const float* img2 = (const float*)d_in[1];
    // d_in[2] (window) unused: weights baked in as compile-time constants.
    float* out = (float*)d_out;

    ssim_main_kernel<<<NBLOCKS, 128>>>(img1, img2);
    ssim_finalize_kernel<<<1, 256>>>(out);
}